// round 8
// baseline (speedup 1.0000x reference)
#include <cuda_runtime.h>
#include <math.h>

#define H 2048
#define VOC 50257

#define NBLK 592                 // exactly 4 blocks/SM * 148 SMs -> co-resident
#define NTHR 256
#define NWARP (NBLK * 8)         // 4736 warps
#define VITERS ((VOC + NWARP - 1) / NWARP)   // 11

// Phase-1 row-task layout: one scalar partial per task, 8 float4-loads/lane.
//   [0, 8192)       : W_ih1 full rows              (K=1024 = 256 f4)
//   [8192, 24576)   : W_hh1 half rows (2 per row)  (half = 256 f4)
//   [24576, 40960)  : W_hh2 half rows (2 per row)
#define NT1 40960
// Phase-2: W_ih2 quarter rows (4 per row), 4 float4-loads/lane
#define NT2 32768

// Scratch (no allocations allowed)
__device__ float g_rowp[NT1];                // per-task scalar partials (reused by P2)
__device__ float g_h1n[H];
__device__ float g_h2n[H];
__device__ float g_gates2[4 * H];
__device__ float g_logits[VOC];
__device__ float g_pm[NBLK];
__device__ float g_ps[NBLK];
__device__ unsigned long long g_ticket = 0;  // monotonic -> replay-safe barrier

__device__ __forceinline__ float warp_sum(float a) {
    #pragma unroll
    for (int o = 16; o > 0; o >>= 1)
        a += __shfl_xor_sync(0xffffffffu, a, o);
    return a;
}
__device__ __forceinline__ float sigmoidf_(float v) {
    return 1.0f / (1.0f + expf(-v));
}

__device__ __forceinline__ void grid_barrier() {
    __syncthreads();
    __threadfence();
    if (threadIdx.x == 0) {
        const unsigned long long my = atomicAdd(&g_ticket, 1ULL);
        const unsigned long long target = (my / NBLK + 1ULL) * NBLK;
        while (atomicAdd(&g_ticket, 0ULL) < target) { }
    }
    __syncthreads();
    __threadfence();
}

// 8-load row segment dot: w/vec at f4 granularity, lanes stride 32.
__device__ __forceinline__ float dot8(const float4* __restrict__ w,
                                      const float4* __restrict__ v, int lane)
{
    float a = 0.0f;
    #pragma unroll
    for (int i = 0; i < 8; i++) {
        const float4 wv = __ldcs(&w[lane + i * 32]);
        const float4 vv = v[lane + i * 32];
        a += wv.x * vv.x + wv.y * vv.y + wv.z * vv.z + wv.w * vv.w;
    }
    return a;
}

__global__ __launch_bounds__(NTHR, 4) void mega_kernel(
    const float* __restrict__ x,     const float* __restrict__ h1,
    const float* __restrict__ c1,    const float* __restrict__ h2,
    const float* __restrict__ c2,
    const float* __restrict__ W_ih1, const float* __restrict__ W_hh1,
    const float* __restrict__ b_ih1, const float* __restrict__ b_hh1,
    const float* __restrict__ W_ih2, const float* __restrict__ W_hh2,
    const float* __restrict__ b_ih2, const float* __restrict__ b_hh2,
    const float* __restrict__ W_out, const float* __restrict__ b_out,
    float* __restrict__ out)
{
    __shared__ float sbuf[5120];     // P1: x|h1|h2 ; P2: h1n ; P3: h2n
    __shared__ float swm[8];
    __shared__ float sws[8];
    __shared__ float sred[256];

    const int tid   = threadIdx.x;
    const int wid   = tid >> 5;
    const int lane  = tid & 31;
    const int wglob = blockIdx.x * 8 + wid;

    // ============================ PHASE 1 ================================
    for (int i = tid; i < 1024; i += NTHR) sbuf[i]        = x[i];
    for (int i = tid; i < 2048; i += NTHR) sbuf[1024 + i] = h1[i];
    for (int i = tid; i < 2048; i += NTHR) sbuf[3072 + i] = h2[i];
    __syncthreads();

    const float4* sx4  = (const float4*)(sbuf);
    const float4* sh14 = (const float4*)(sbuf + 1024);
    const float4* sh24 = (const float4*)(sbuf + 3072);

    for (int t = wglob; t < NT1; t += NWARP) {
        const float4* w;
        const float4* v;
        if (t < 8192) {
            // W_ih1 full row (256 f4)
            w = (const float4*)W_ih1 + (size_t)t * 256;
            v = sx4;
        } else if (t < 24576) {
            const int q = t - 8192;
            const int off = (q & 1) * 256;
            w = (const float4*)W_hh1 + (size_t)(q >> 1) * 512 + off;
            v = sh14 + off;
        } else {
            const int q = t - 24576;
            const int off = (q & 1) * 256;
            w = (const float4*)W_hh2 + (size_t)(q >> 1) * 512 + off;
            v = sh24 + off;
        }
        float a = dot8(w, v, lane);
        a = warp_sum(a);
        if (lane == 0) g_rowp[t] = a;
    }

    grid_barrier();   // all P1 row partials visible

    // ============================ PHASE 1b ===============================
    // warps [0,2048): layer-1 cell for unit u; lanes 0-3 assemble gate sums.
    if (wglob < 2048) {
        const int u = wglob;
        float gs = 0.0f;
        if (lane < 4) {
            const int r = lane * H + u;   // gate row index
            gs = g_rowp[r]                      // ih1 full row
               + g_rowp[8192 + 2 * r]           // hh1 half 0
               + g_rowp[8192 + 2 * r + 1]       // hh1 half 1
               + b_ih1[r] + b_hh1[r];
        }
        const float gi = __shfl_sync(0xffffffffu, gs, 0);
        const float gf = __shfl_sync(0xffffffffu, gs, 1);
        const float gg = __shfl_sync(0xffffffffu, gs, 2);
        const float go = __shfl_sync(0xffffffffu, gs, 3);
        if (lane == 0) {
            const float iv = sigmoidf_(gi), fv = sigmoidf_(gf);
            const float gv = tanhf(gg),     ov = sigmoidf_(go);
            const float cn = fv * c1[u] + iv * gv;
            g_h1n[u] = ov * tanhf(cn);
        }
    } else if (wglob < 4096) {
        // warps [2048,4096): gates2[r] = hh2 partial + biases (lanes 0-3 write)
        const int u = wglob - 2048;
        if (lane < 4) {
            const int r = lane * H + u;
            g_gates2[r] = g_rowp[24576 + 2 * r] + g_rowp[24576 + 2 * r + 1]
                        + b_ih2[r] + b_hh2[r];
        }
    }

    grid_barrier();   // h1n + gates2 ready; g_rowp free for reuse

    // ============================ PHASE 2 ================================
    for (int i = tid; i < 2048; i += NTHR) sbuf[i] = g_h1n[i];
    __syncthreads();
    const float4* sg4 = (const float4*)sbuf;

    for (int t = wglob; t < NT2; t += NWARP) {
        const int r   = t >> 2;
        const int off = (t & 3) * 128;
        const float4* w = (const float4*)W_ih2 + (size_t)r * 512 + off;
        const float4* v = sg4 + off;
        float a = 0.0f;
        #pragma unroll
        for (int i = 0; i < 4; i++) {
            const float4 wv = __ldcs(&w[lane + i * 32]);
            const float4 vv = v[lane + i * 32];
            a += wv.x * vv.x + wv.y * vv.y + wv.z * vv.z + wv.w * vv.w;
        }
        a = warp_sum(a);
        if (lane == 0) g_rowp[t] = a;
    }

    grid_barrier();   // P2 partials complete

    // ============================ PHASE 2b ===============================
    if (wglob < 2048) {
        const int u = wglob;
        float gs = 0.0f;
        if (lane < 4) {
            const int r = lane * H + u;
            gs = g_rowp[4 * r] + g_rowp[4 * r + 1]
               + g_rowp[4 * r + 2] + g_rowp[4 * r + 3]
               + g_gates2[r];
        }
        const float gi = __shfl_sync(0xffffffffu, gs, 0);
        const float gf = __shfl_sync(0xffffffffu, gs, 1);
        const float gg = __shfl_sync(0xffffffffu, gs, 2);
        const float go = __shfl_sync(0xffffffffu, gs, 3);
        if (lane == 0) {
            const float iv = sigmoidf_(gi), fv = sigmoidf_(gf);
            const float gv = tanhf(gg),     ov = sigmoidf_(go);
            const float cn = fv * c2[u] + iv * gv;
            g_h2n[u] = ov * tanhf(cn);
        }
    }

    grid_barrier();   // h2n ready

    // ============================ PHASE 3 ================================
    __syncthreads();
    for (int i = tid; i < 2048; i += NTHR) sbuf[i] = g_h2n[i];
    __syncthreads();
    const float4* sh4 = (const float4*)sbuf;

    float m = -INFINITY, s = 0.0f;
    for (int it = 0; it < VITERS; it++) {
        const int row = wglob + it * NWARP;
        if (row < VOC) {
            const float4* w4 = (const float4*)(W_out + (size_t)row * 2048);
            float a = 0.0f;
            #pragma unroll 8
            for (int j = lane; j < 512; j += 32) {
                float4 wv = __ldcs(&w4[j]); float4 hv = sh4[j];
                a += wv.x * hv.x + wv.y * hv.y + wv.z * hv.z + wv.w * hv.w;
            }
            a = warp_sum(a);
            const float v = a + __ldg(&b_out[row]);
            if (lane == 0) g_logits[row] = v;
            const float nm = fmaxf(m, v);
            s = s * expf(m - nm) + expf(v - nm);
            m = nm;
        }
    }
    if (lane == 0) { swm[wid] = m; sws[wid] = s; }
    __syncthreads();

    if (tid == 0) {
        float bm = -INFINITY;
        #pragma unroll
        for (int i = 0; i < 8; i++) bm = fmaxf(bm, swm[i]);
        float bs = 0.0f;
        #pragma unroll
        for (int i = 0; i < 8; i++)
            bs += (swm[i] == -INFINITY) ? 0.0f : sws[i] * expf(swm[i] - bm);
        g_pm[blockIdx.x] = bm;
        g_ps[blockIdx.x] = bs;
    }

    grid_barrier();   // all (m,s) partials visible

    float lm = -INFINITY;
    for (int i = tid; i < NBLK; i += NTHR) lm = fmaxf(lm, g_pm[i]);
    sred[tid] = lm;
    __syncthreads();
    for (int st = 128; st > 0; st >>= 1) {
        if (tid < st) sred[tid] = fmaxf(sred[tid], sred[tid + st]);
        __syncthreads();
    }
    const float M = sred[0];
    __syncthreads();

    float ls = 0.0f;
    for (int i = tid; i < NBLK; i += NTHR)
        ls += (g_pm[i] == -INFINITY) ? 0.0f : g_ps[i] * expf(g_pm[i] - M);
    sred[tid] = ls;
    __syncthreads();
    for (int st = 128; st > 0; st >>= 1) {
        if (tid < st) sred[tid] += sred[tid + st];
        __syncthreads();
    }
    const float shift = M + logf(sred[0]);

    for (int i = blockIdx.x * NTHR + tid; i < VOC; i += NBLK * NTHR)
        out[i] = g_logits[i] - shift;
}

// ---------------------------------------------------------------------------
extern "C" void kernel_launch(void* const* d_in, const int* in_sizes, int n_in,
                              void* d_out, int out_size)
{
    const float* x     = (const float*)d_in[0];
    const float* h1    = (const float*)d_in[1];
    const float* c1    = (const float*)d_in[2];
    const float* h2    = (const float*)d_in[3];
    const float* c2    = (const float*)d_in[4];
    const float* W_ih1 = (const float*)d_in[5];
    const float* W_hh1 = (const float*)d_in[6];
    const float* b_ih1 = (const float*)d_in[7];
    const float* b_hh1 = (const float*)d_in[8];
    const float* W_ih2 = (const float*)d_in[9];
    const float* W_hh2 = (const float*)d_in[10];
    const float* b_ih2 = (const float*)d_in[11];
    const float* b_hh2 = (const float*)d_in[12];
    const float* W_out = (const float*)d_in[13];
    const float* b_out = (const float*)d_in[14];
    float* out = (float*)d_out;

    mega_kernel<<<NBLK, NTHR>>>(x, h1, c1, h2, c2,
                                W_ih1, W_hh1, b_ih1, b_hh1,
                                W_ih2, W_hh2, b_ih2, b_hh2,
                                W_out, b_out, out);
}

// round 9
// speedup vs baseline: 1.0175x; 1.0175x over previous
#include <cuda_runtime.h>
#include <math.h>

#define H 2048
#define VOC 50257

// Stage A/B: 512 blocks x 8 warps = 4096 warps; tasks divide exactly.
#define ABLK 512
#define ATHR 256
#define AWARP (ABLK * 8)          // 4096
#define NT_A 20480                // 4096 ih1-pair + 8192 hh1 + 8192 hh2 (5/warp)
#define NT_B 8192                 // W_ih2 rows (2/warp)

// Vocab: persistent 592 blocks (<= 148 SMs * 4)
#define VBLK 592
#define VTHR 256
#define VWARP (VBLK * 8)          // 4736
#define VITERS ((VOC + VWARP - 1) / VWARP)   // 11

// Scratch (no allocations allowed)
__device__ float g_pih1[4 * H];   // W_ih1[r]·x
__device__ float g_phh1[4 * H];   // W_hh1[r]·h1
__device__ float g_phh2[4 * H];   // W_hh2[r]·h2
__device__ float g_pih2[4 * H];   // W_ih2[r]·h1n
__device__ float g_gates2[4 * H]; // phh2 + b_ih2 + b_hh2
__device__ float g_h1n[H];
__device__ float g_h2n[H];
__device__ float g_logits[VOC];
__device__ float g_pm[VBLK];
__device__ float g_ps[VBLK];
__device__ unsigned long long g_tickB = 0;   // monotonic -> replay-safe
__device__ unsigned long long g_tickV = 0;

__device__ __forceinline__ float warp_sum(float a) {
    #pragma unroll
    for (int o = 16; o > 0; o >>= 1)
        a += __shfl_xor_sync(0xffffffffu, a, o);
    return a;
}
__device__ __forceinline__ float sigmoidf_(float v) {
    return 1.0f / (1.0f + expf(-v));
}
__device__ __forceinline__ void grid_barrier(unsigned long long* tick, int nblk) {
    __syncthreads();
    __threadfence();
    if (threadIdx.x == 0) {
        const unsigned long long my = atomicAdd(tick, 1ULL);
        const unsigned long long target = (my / (unsigned long long)nblk + 1ULL)
                                          * (unsigned long long)nblk;
        while (atomicAdd(tick, 0ULL) < target) { }
    }
    __syncthreads();
    __threadfence();
}

// ---------------------------------------------------------------------------
// Stage A: 20480 uniform 8KB warp-tasks, exactly 5 per warp. Each task is the
// proven vocab-style loop: 16 independent contiguous float4 loads -> 1 (or 2)
// warp_sum. Writes per-row scalar partials.
// ---------------------------------------------------------------------------
__global__ __launch_bounds__(ATHR, 4) void stageA_kernel(
    const float* __restrict__ x,  const float* __restrict__ h1,
    const float* __restrict__ h2,
    const float* __restrict__ W_ih1, const float* __restrict__ W_hh1,
    const float* __restrict__ W_hh2)
{
    __shared__ float sbuf[5120];    // x | h1 | h2
    const int tid  = threadIdx.x;
    const int wid  = tid >> 5;
    const int lane = tid & 31;
    const int wglob = blockIdx.x * 8 + wid;

    for (int i = tid; i < 1024; i += ATHR) sbuf[i]        = x[i];
    for (int i = tid; i < 2048; i += ATHR) sbuf[1024 + i] = h1[i];
    for (int i = tid; i < 2048; i += ATHR) sbuf[3072 + i] = h2[i];
    __syncthreads();

    const float4* sx4  = (const float4*)(sbuf);
    const float4* sh14 = (const float4*)(sbuf + 1024);
    const float4* sh24 = (const float4*)(sbuf + 3072);

    #pragma unroll 1
    for (int t = wglob; t < NT_A; t += AWARP) {
        if (t < 4096) {
            // W_ih1 row pair (r0, r0+1): 2 x 256 f4, 16 loads, 2 sums
            const int r0 = 2 * t;
            const float4* w0 = (const float4*)W_ih1 + (size_t)r0 * 256;
            const float4* w1 = w0 + 256;
            float a0 = 0.f, a1 = 0.f;
            #pragma unroll
            for (int i = 0; i < 8; i++) {
                const int j = lane + i * 32;
                const float4 v  = sx4[j];
                const float4 p0 = __ldcs(&w0[j]);
                const float4 p1 = __ldcs(&w1[j]);
                a0 += p0.x*v.x + p0.y*v.y + p0.z*v.z + p0.w*v.w;
                a1 += p1.x*v.x + p1.y*v.y + p1.z*v.z + p1.w*v.w;
            }
            a0 = warp_sum(a0); a1 = warp_sum(a1);
            if (lane == 0) { g_pih1[r0] = a0; g_pih1[r0 + 1] = a1; }
        } else if (t < 12288) {
            // W_hh1 full row: 512 f4, 16 loads, 1 sum
            const int r = t - 4096;
            const float4* w = (const float4*)W_hh1 + (size_t)r * 512;
            float a = 0.f;
            #pragma unroll 8
            for (int j = lane; j < 512; j += 32) {
                const float4 p = __ldcs(&w[j]);
                const float4 v = sh14[j];
                a += p.x*v.x + p.y*v.y + p.z*v.z + p.w*v.w;
            }
            a = warp_sum(a);
            if (lane == 0) g_phh1[r] = a;
        } else {
            // W_hh2 full row
            const int r = t - 12288;
            const float4* w = (const float4*)W_hh2 + (size_t)r * 512;
            float a = 0.f;
            #pragma unroll 8
            for (int j = lane; j < 512; j += 32) {
                const float4 p = __ldcs(&w[j]);
                const float4 v = sh24[j];
                a += p.x*v.x + p.y*v.y + p.z*v.z + p.w*v.w;
            }
            a = warp_sum(a);
            if (lane == 0) g_phh2[r] = a;
        }
    }
}

// ---------------------------------------------------------------------------
// Stage B: prologue (layer-1 cell + gates2 assembly) -> barrier -> W_ih2 GEMV.
// 512 blocks co-resident (<= 592), exactly 2 row-tasks per warp.
// ---------------------------------------------------------------------------
__global__ __launch_bounds__(ATHR, 4) void stageB_kernel(
    const float* __restrict__ W_ih2,
    const float* __restrict__ b_ih1, const float* __restrict__ b_hh1,
    const float* __restrict__ c1,
    const float* __restrict__ b_ih2, const float* __restrict__ b_hh2)
{
    __shared__ float sh[2048];
    const int tid  = threadIdx.x;
    const int wid  = tid >> 5;
    const int lane = tid & 31;
    const int wglob = blockIdx.x * 8 + wid;

    // ---- prologue: spread across 64 blocks for parallel MUFU ----
    if (blockIdx.x < 32) {
        if (tid < 64) {
            const int u = blockIdx.x * 64 + tid;   // 2048 units
            const float gi = g_pih1[u        ] + g_phh1[u        ] + b_ih1[u        ] + b_hh1[u        ];
            const float gf = g_pih1[u +     H] + g_phh1[u +     H] + b_ih1[u +     H] + b_hh1[u +     H];
            const float gg = g_pih1[u + 2 * H] + g_phh1[u + 2 * H] + b_ih1[u + 2 * H] + b_hh1[u + 2 * H];
            const float go = g_pih1[u + 3 * H] + g_phh1[u + 3 * H] + b_ih1[u + 3 * H] + b_hh1[u + 3 * H];
            const float iv = sigmoidf_(gi), fv = sigmoidf_(gf);
            const float gv = tanhf(gg),     ov = sigmoidf_(go);
            const float cn = fv * c1[u] + iv * gv;
            g_h1n[u] = ov * tanhf(cn);
        }
    } else if (blockIdx.x < 64) {
        const int r = (blockIdx.x - 32) * 256 + tid;   // 8192 gate rows
        g_gates2[r] = g_phh2[r] + b_ih2[r] + b_hh2[r];
    }

    grid_barrier(&g_tickB, ABLK);   // h1n + gates2 ready

    for (int i = tid; i < 2048; i += ATHR) sh[i] = g_h1n[i];
    __syncthreads();
    const float4* sh4 = (const float4*)sh;

    #pragma unroll 1
    for (int t = wglob; t < NT_B; t += AWARP) {
        const float4* w = (const float4*)W_ih2 + (size_t)t * 512;
        float a = 0.f;
        #pragma unroll 8
        for (int j = lane; j < 512; j += 32) {
            const float4 p = __ldcs(&w[j]);
            const float4 v = sh4[j];
            a += p.x*v.x + p.y*v.y + p.z*v.z + p.w*v.w;
        }
        a = warp_sum(a);
        if (lane == 0) g_pih2[t] = a;
    }
}

// ---------------------------------------------------------------------------
// Vocab: prologue (layer-2 cell) -> barrier -> GEMV + logsumexp + output.
// 592 blocks co-resident; ticket barrier used twice per launch (replay-safe).
// ---------------------------------------------------------------------------
__global__ __launch_bounds__(VTHR, 4) void vocab_kernel(
    const float* __restrict__ W, const float* __restrict__ b,
    const float* __restrict__ c2, float* __restrict__ out)
{
    __shared__ float sh[2048];
    __shared__ float swm[8];
    __shared__ float sws[8];
    __shared__ float sred[256];

    const int tid  = threadIdx.x;
    const int wid  = tid >> 5;
    const int lane = tid & 31;
    const int wglob = blockIdx.x * 8 + wid;

    // ---- prologue: layer-2 cell on 32 blocks ----
    if (blockIdx.x < 32 && tid < 64) {
        const int u = blockIdx.x * 64 + tid;
        const float gi = g_pih2[u        ] + g_gates2[u        ];
        const float gf = g_pih2[u +     H] + g_gates2[u +     H];
        const float gg = g_pih2[u + 2 * H] + g_gates2[u + 2 * H];
        const float go = g_pih2[u + 3 * H] + g_gates2[u + 3 * H];
        const float iv = sigmoidf_(gi), fv = sigmoidf_(gf);
        const float gv = tanhf(gg),     ov = sigmoidf_(go);
        const float cn = fv * c2[u] + iv * gv;
        g_h2n[u] = ov * tanhf(cn);
    }

    grid_barrier(&g_tickV, VBLK);   // h2n ready

    for (int i = tid; i < 2048; i += VTHR) sh[i] = g_h2n[i];
    __syncthreads();
    const float4* sh4 = (const float4*)sh;

    float m = -INFINITY, s = 0.0f;
    for (int it = 0; it < VITERS; it++) {
        const int row = wglob + it * VWARP;
        if (row < VOC) {
            const float4* w4 = (const float4*)(W + (size_t)row * 2048);
            float a = 0.0f;
            #pragma unroll 8
            for (int j = lane; j < 512; j += 32) {
                float4 wv = __ldcs(&w4[j]); float4 hv = sh4[j];
                a += wv.x * hv.x + wv.y * hv.y + wv.z * hv.z + wv.w * hv.w;
            }
            a = warp_sum(a);
            const float v = a + __ldg(&b[row]);
            if (lane == 0) g_logits[row] = v;
            const float nm = fmaxf(m, v);
            s = s * expf(m - nm) + expf(v - nm);
            m = nm;
        }
    }
    if (lane == 0) { swm[wid] = m; sws[wid] = s; }
    __syncthreads();

    if (tid == 0) {
        float bm = -INFINITY;
        #pragma unroll
        for (int i = 0; i < 8; i++) bm = fmaxf(bm, swm[i]);
        float bs = 0.0f;
        #pragma unroll
        for (int i = 0; i < 8; i++)
            bs += (swm[i] == -INFINITY) ? 0.0f : sws[i] * expf(swm[i] - bm);
        g_pm[blockIdx.x] = bm;
        g_ps[blockIdx.x] = bs;
    }

    grid_barrier(&g_tickV, VBLK);   // all (m,s) partials visible

    float lm = -INFINITY;
    for (int i = tid; i < VBLK; i += VTHR) lm = fmaxf(lm, g_pm[i]);
    sred[tid] = lm;
    __syncthreads();
    for (int st = 128; st > 0; st >>= 1) {
        if (tid < st) sred[tid] = fmaxf(sred[tid], sred[tid + st]);
        __syncthreads();
    }
    const float M = sred[0];
    __syncthreads();

    float ls = 0.0f;
    for (int i = tid; i < VBLK; i += VTHR)
        ls += (g_pm[i] == -INFINITY) ? 0.0f : g_ps[i] * expf(g_pm[i] - M);
    sred[tid] = ls;
    __syncthreads();
    for (int st = 128; st > 0; st >>= 1) {
        if (tid < st) sred[tid] += sred[tid + st];
        __syncthreads();
    }
    const float shift = M + logf(sred[0]);

    for (int i = blockIdx.x * VTHR + tid; i < VOC; i += VBLK * VTHR)
        out[i] = g_logits[i] - shift;
}

// ---------------------------------------------------------------------------
extern "C" void kernel_launch(void* const* d_in, const int* in_sizes, int n_in,
                              void* d_out, int out_size)
{
    const float* x     = (const float*)d_in[0];
    const float* h1    = (const float*)d_in[1];
    const float* c1    = (const float*)d_in[2];
    const float* h2    = (const float*)d_in[3];
    const float* c2    = (const float*)d_in[4];
    const float* W_ih1 = (const float*)d_in[5];
    const float* W_hh1 = (const float*)d_in[6];
    const float* b_ih1 = (const float*)d_in[7];
    const float* b_hh1 = (const float*)d_in[8];
    const float* W_ih2 = (const float*)d_in[9];
    const float* W_hh2 = (const float*)d_in[10];
    const float* b_ih2 = (const float*)d_in[11];
    const float* b_hh2 = (const float*)d_in[12];
    const float* W_out = (const float*)d_in[13];
    const float* b_out = (const float*)d_in[14];
    float* out = (float*)d_out;

    // A: all row partials that depend only on inputs (ih1, hh1, hh2)
    stageA_kernel<<<ABLK, ATHR>>>(x, h1, h2, W_ih1, W_hh1, W_hh2);
    // B: layer-1 cell + gates2 (prologue) -> barrier -> W_ih2 GEMV
    stageB_kernel<<<ABLK, ATHR>>>(W_ih2, b_ih1, b_hh1, c1, b_ih2, b_hh2);
    // V: layer-2 cell (prologue) -> barrier -> vocab GEMV + log-softmax
    vocab_kernel<<<VBLK, VTHR>>>(W_out, b_out, c2, out);
}

// round 10
// speedup vs baseline: 1.0497x; 1.0317x over previous
#include <cuda_runtime.h>
#include <math.h>

#define H 2048
#define VOC 50257

// All GEMV kernels: 592 blocks x 8 warps (4 blocks/SM on 148 SMs -> co-resident,
// also co-resident on a 152-SM part). 4736 warps.
#define NBLK 592
#define NTHR 256
#define NWARP (NBLK * 8)          // 4736
#define VITERS ((VOC + NWARP - 1) / NWARP)   // 11

#define NT_A 20480                // 4096 ih1-pair + 8192 hh1 + 8192 hh2 tasks
#define NT_B 8192                 // W_ih2 rows

// Scratch (no allocations allowed)
__device__ float g_pih1[4 * H];   // W_ih1[r]·x
__device__ float g_phh1[4 * H];   // W_hh1[r]·h1
__device__ float g_phh2[4 * H];   // W_hh2[r]·h2
__device__ float g_pih2[4 * H];   // W_ih2[r]·h1n
__device__ float g_gates2[4 * H]; // phh2 + b_ih2 + b_hh2
__device__ float g_h1n[H];
__device__ float g_h2n[H];
__device__ float g_logits[VOC];
__device__ float g_pm[NBLK];
__device__ float g_ps[NBLK];
__device__ unsigned long long g_tickB = 0;   // monotonic -> replay-safe
__device__ unsigned long long g_tickV = 0;

__device__ __forceinline__ float warp_sum(float a) {
    #pragma unroll
    for (int o = 16; o > 0; o >>= 1)
        a += __shfl_xor_sync(0xffffffffu, a, o);
    return a;
}
__device__ __forceinline__ float sigmoidf_(float v) {
    return 1.0f / (1.0f + expf(-v));
}
__device__ __forceinline__ void grid_barrier(unsigned long long* tick, int nblk) {
    __syncthreads();
    __threadfence();
    if (threadIdx.x == 0) {
        const unsigned long long my = atomicAdd(tick, 1ULL);
        const unsigned long long target = (my / (unsigned long long)nblk + 1ULL)
                                          * (unsigned long long)nblk;
        while (atomicAdd(tick, 0ULL) < target) { }
    }
    __syncthreads();
    __threadfence();
}

// ---------------------------------------------------------------------------
// Stage A: 20480 uniform 16-load warp-tasks strided over 4736 warps.
// Heavy (5-task) warps live in blocks 0-191, which scatter round-robin across
// SMs -> per-SM imbalance only ~4-8% while occupancy is 4 blocks/SM everywhere.
// ---------------------------------------------------------------------------
__global__ __launch_bounds__(NTHR, 4) void stageA_kernel(
    const float* __restrict__ x,  const float* __restrict__ h1,
    const float* __restrict__ h2,
    const float* __restrict__ W_ih1, const float* __restrict__ W_hh1,
    const float* __restrict__ W_hh2)
{
    __shared__ float sbuf[5120];    // x | h1 | h2
    const int tid  = threadIdx.x;
    const int wid  = tid >> 5;
    const int lane = tid & 31;
    const int wglob = blockIdx.x * 8 + wid;

    for (int i = tid; i < 1024; i += NTHR) sbuf[i]        = x[i];
    for (int i = tid; i < 2048; i += NTHR) sbuf[1024 + i] = h1[i];
    for (int i = tid; i < 2048; i += NTHR) sbuf[3072 + i] = h2[i];
    __syncthreads();

    const float4* sx4  = (const float4*)(sbuf);
    const float4* sh14 = (const float4*)(sbuf + 1024);
    const float4* sh24 = (const float4*)(sbuf + 3072);

    #pragma unroll 1
    for (int t = wglob; t < NT_A; t += NWARP) {
        if (t < 4096) {
            // W_ih1 row pair (2t, 2t+1): 2 x 256 f4, 16 loads, 2 sums
            const int r0 = 2 * t;
            const float4* w0 = (const float4*)W_ih1 + (size_t)r0 * 256;
            const float4* w1 = w0 + 256;
            float a0 = 0.f, a1 = 0.f;
            #pragma unroll
            for (int i = 0; i < 8; i++) {
                const int j = lane + i * 32;
                const float4 v  = sx4[j];
                const float4 p0 = __ldcs(&w0[j]);
                const float4 p1 = __ldcs(&w1[j]);
                a0 += p0.x*v.x + p0.y*v.y + p0.z*v.z + p0.w*v.w;
                a1 += p1.x*v.x + p1.y*v.y + p1.z*v.z + p1.w*v.w;
            }
            a0 = warp_sum(a0); a1 = warp_sum(a1);
            if (lane == 0) { g_pih1[r0] = a0; g_pih1[r0 + 1] = a1; }
        } else if (t < 12288) {
            // W_hh1 full row: 512 f4, 16 loads, 1 sum
            const int r = t - 4096;
            const float4* w = (const float4*)W_hh1 + (size_t)r * 512;
            float a = 0.f;
            #pragma unroll 8
            for (int j = lane; j < 512; j += 32) {
                const float4 p = __ldcs(&w[j]);
                const float4 v = sh14[j];
                a += p.x*v.x + p.y*v.y + p.z*v.z + p.w*v.w;
            }
            a = warp_sum(a);
            if (lane == 0) g_phh1[r] = a;
        } else {
            // W_hh2 full row
            const int r = t - 12288;
            const float4* w = (const float4*)W_hh2 + (size_t)r * 512;
            float a = 0.f;
            #pragma unroll 8
            for (int j = lane; j < 512; j += 32) {
                const float4 p = __ldcs(&w[j]);
                const float4 v = sh24[j];
                a += p.x*v.x + p.y*v.y + p.z*v.z + p.w*v.w;
            }
            a = warp_sum(a);
            if (lane == 0) g_phh2[r] = a;
        }
    }
}

// ---------------------------------------------------------------------------
// Stage B: prologue (layer-1 cell + gates2 assembly) -> barrier -> W_ih2 GEMV.
// 592 blocks co-resident; 8192 row-tasks (1-2 per warp).
// ---------------------------------------------------------------------------
__global__ __launch_bounds__(NTHR, 4) void stageB_kernel(
    const float* __restrict__ W_ih2,
    const float* __restrict__ b_ih1, const float* __restrict__ b_hh1,
    const float* __restrict__ c1,
    const float* __restrict__ b_ih2, const float* __restrict__ b_hh2)
{
    __shared__ float sh[2048];
    const int tid  = threadIdx.x;
    const int wid  = tid >> 5;
    const int lane = tid & 31;
    const int wglob = blockIdx.x * 8 + wid;

    // ---- prologue: spread cell math / gates2 across 64 blocks ----
    if (blockIdx.x < 32) {
        if (tid < 64) {
            const int u = blockIdx.x * 64 + tid;   // 2048 units
            const float gi = g_pih1[u        ] + g_phh1[u        ] + b_ih1[u        ] + b_hh1[u        ];
            const float gf = g_pih1[u +     H] + g_phh1[u +     H] + b_ih1[u +     H] + b_hh1[u +     H];
            const float gg = g_pih1[u + 2 * H] + g_phh1[u + 2 * H] + b_ih1[u + 2 * H] + b_hh1[u + 2 * H];
            const float go = g_pih1[u + 3 * H] + g_phh1[u + 3 * H] + b_ih1[u + 3 * H] + b_hh1[u + 3 * H];
            const float iv = sigmoidf_(gi), fv = sigmoidf_(gf);
            const float gv = tanhf(gg),     ov = sigmoidf_(go);
            const float cn = fv * c1[u] + iv * gv;
            g_h1n[u] = ov * tanhf(cn);
        }
    } else if (blockIdx.x < 64) {
        const int r = (blockIdx.x - 32) * 256 + tid;   // 8192 gate rows
        g_gates2[r] = g_phh2[r] + b_ih2[r] + b_hh2[r];
    }

    grid_barrier(&g_tickB, NBLK);   // h1n + gates2 ready

    for (int i = tid; i < 2048; i += NTHR) sh[i] = g_h1n[i];
    __syncthreads();
    const float4* sh4 = (const float4*)sh;

    #pragma unroll 1
    for (int t = wglob; t < NT_B; t += NWARP) {
        const float4* w = (const float4*)W_ih2 + (size_t)t * 512;
        float a = 0.f;
        #pragma unroll 8
        for (int j = lane; j < 512; j += 32) {
            const float4 p = __ldcs(&w[j]);
            const float4 v = sh4[j];
            a += p.x*v.x + p.y*v.y + p.z*v.z + p.w*v.w;
        }
        a = warp_sum(a);
        if (lane == 0) g_pih2[t] = a;
    }
}

// ---------------------------------------------------------------------------
// Vocab: prologue (layer-2 cell) -> barrier -> GEMV + logsumexp + output.
// 592 blocks co-resident; ticket barrier used twice per launch (replay-safe).
// ---------------------------------------------------------------------------
__global__ __launch_bounds__(NTHR, 4) void vocab_kernel(
    const float* __restrict__ W, const float* __restrict__ b,
    const float* __restrict__ c2, float* __restrict__ out)
{
    __shared__ float sh[2048];
    __shared__ float swm[8];
    __shared__ float sws[8];
    __shared__ float sred[256];

    const int tid  = threadIdx.x;
    const int wid  = tid >> 5;
    const int lane = tid & 31;
    const int wglob = blockIdx.x * 8 + wid;

    // ---- prologue: layer-2 cell on 32 blocks ----
    if (blockIdx.x < 32 && tid < 64) {
        const int u = blockIdx.x * 64 + tid;
        const float gi = g_pih2[u        ] + g_gates2[u        ];
        const float gf = g_pih2[u +     H] + g_gates2[u +     H];
        const float gg = g_pih2[u + 2 * H] + g_gates2[u + 2 * H];
        const float go = g_pih2[u + 3 * H] + g_gates2[u + 3 * H];
        const float iv = sigmoidf_(gi), fv = sigmoidf_(gf);
        const float gv = tanhf(gg),     ov = sigmoidf_(go);
        const float cn = fv * c2[u] + iv * gv;
        g_h2n[u] = ov * tanhf(cn);
    }

    grid_barrier(&g_tickV, NBLK);   // h2n ready

    for (int i = tid; i < 2048; i += NTHR) sh[i] = g_h2n[i];
    __syncthreads();
    const float4* sh4 = (const float4*)sh;

    float m = -INFINITY, s = 0.0f;
    for (int it = 0; it < VITERS; it++) {
        const int row = wglob + it * NWARP;
        if (row < VOC) {
            const float4* w4 = (const float4*)(W + (size_t)row * 2048);
            float a = 0.0f;
            #pragma unroll 8
            for (int j = lane; j < 512; j += 32) {
                float4 wv = __ldcs(&w4[j]); float4 hv = sh4[j];
                a += wv.x * hv.x + wv.y * hv.y + wv.z * hv.z + wv.w * hv.w;
            }
            a = warp_sum(a);
            const float v = a + __ldg(&b[row]);
            if (lane == 0) g_logits[row] = v;
            const float nm = fmaxf(m, v);
            s = s * expf(m - nm) + expf(v - nm);
            m = nm;
        }
    }
    if (lane == 0) { swm[wid] = m; sws[wid] = s; }
    __syncthreads();

    if (tid == 0) {
        float bm = -INFINITY;
        #pragma unroll
        for (int i = 0; i < 8; i++) bm = fmaxf(bm, swm[i]);
        float bs = 0.0f;
        #pragma unroll
        for (int i = 0; i < 8; i++)
            bs += (swm[i] == -INFINITY) ? 0.0f : sws[i] * expf(swm[i] - bm);
        g_pm[blockIdx.x] = bm;
        g_ps[blockIdx.x] = bs;
    }

    grid_barrier(&g_tickV, NBLK);   // all (m,s) partials visible

    float lm = -INFINITY;
    for (int i = tid; i < NBLK; i += NTHR) lm = fmaxf(lm, g_pm[i]);
    sred[tid] = lm;
    __syncthreads();
    for (int st = 128; st > 0; st >>= 1) {
        if (tid < st) sred[tid] = fmaxf(sred[tid], sred[tid + st]);
        __syncthreads();
    }
    const float M = sred[0];
    __syncthreads();

    float ls = 0.0f;
    for (int i = tid; i < NBLK; i += NTHR)
        ls += (g_pm[i] == -INFINITY) ? 0.0f : g_ps[i] * expf(g_pm[i] - M);
    sred[tid] = ls;
    __syncthreads();
    for (int st = 128; st > 0; st >>= 1) {
        if (tid < st) sred[tid] += sred[tid + st];
        __syncthreads();
    }
    const float shift = M + logf(sred[0]);

    for (int i = blockIdx.x * NTHR + tid; i < VOC; i += NBLK * NTHR)
        out[i] = g_logits[i] - shift;
}

// ---------------------------------------------------------------------------
extern "C" void kernel_launch(void* const* d_in, const int* in_sizes, int n_in,
                              void* d_out, int out_size)
{
    const float* x     = (const float*)d_in[0];
    const float* h1    = (const float*)d_in[1];
    const float* c1    = (const float*)d_in[2];
    const float* h2    = (const float*)d_in[3];
    const float* c2    = (const float*)d_in[4];
    const float* W_ih1 = (const float*)d_in[5];
    const float* W_hh1 = (const float*)d_in[6];
    const float* b_ih1 = (const float*)d_in[7];
    const float* b_hh1 = (const float*)d_in[8];
    const float* W_ih2 = (const float*)d_in[9];
    const float* W_hh2 = (const float*)d_in[10];
    const float* b_ih2 = (const float*)d_in[11];
    const float* b_hh2 = (const float*)d_in[12];
    const float* W_out = (const float*)d_in[13];
    const float* b_out = (const float*)d_in[14];
    float* out = (float*)d_out;

    // A: all row partials that depend only on inputs (ih1, hh1, hh2)
    stageA_kernel<<<NBLK, NTHR>>>(x, h1, h2, W_ih1, W_hh1, W_hh2);
    // B: layer-1 cell + gates2 (prologue) -> barrier -> W_ih2 GEMV
    stageB_kernel<<<NBLK, NTHR>>>(W_ih2, b_ih1, b_hh1, c1, b_ih2, b_hh2);
    // V: layer-2 cell (prologue) -> barrier -> vocab GEMV + log-softmax
    vocab_kernel<<<NBLK, NTHR>>>(W_out, b_out, c2, out);
}